// round 1
// baseline (speedup 1.0000x reference)
#include <cuda_runtime.h>
#include <cuda_bf16.h>

// ---------------------------------------------------------------------------
// SimpleSNN: out = f( x@W1^T ) @ W2^T
//   cur = (x@W1^T + b1)/T        [B,H]
//   32-step LIF loop -> total_spikes [B,H]
//   output = total_spikes@W2^T + b2   [B,OUT]
// d_out layout: [ output (B*OUT) | total_spikes (B*H) ]
// ---------------------------------------------------------------------------

#define BM1 128
#define BN1 128
#define BK1 8

__global__ __launch_bounds__(256)
void snn_fc1_lif_kernel(const float* __restrict__ x,     // [B, IN]
                        const float* __restrict__ W1,    // [H, IN]
                        const float* __restrict__ b1,    // [H]
                        const float* __restrict__ tau_mem,
                        const float* __restrict__ tau_syn,
                        const float* __restrict__ v_thresh,
                        const float* __restrict__ v_reset,
                        const float* __restrict__ v0,    // [B, H]
                        const float* __restrict__ i0,    // [B, H]
                        const int*   __restrict__ tsteps,
                        float* __restrict__ spikes,      // [B, H]
                        int Bn, int IN, int H)
{
    __shared__ __align__(16) float As[BK1][BM1 + 4];
    __shared__ __align__(16) float Bs[BK1][BN1 + 4];

    const int tid = threadIdx.x;
    const int tx  = tid & 15;   // 0..15  (col group)
    const int ty  = tid >> 4;   // 0..15  (row group)
    const int m0  = blockIdx.y * BM1;
    const int n0  = blockIdx.x * BN1;

    // global-load mapping: 256 threads x 1 float4 per 128x8 tile
    const int arow = tid >> 1;        // 0..127
    const int acol = (tid & 1) * 4;   // 0 or 4

    float acc[8][8];
#pragma unroll
    for (int i = 0; i < 8; i++)
#pragma unroll
        for (int j = 0; j < 8; j++) acc[i][j] = 0.0f;

    const int ktiles = IN / BK1;
    for (int kt = 0; kt < ktiles; kt++) {
        const int k0 = kt * BK1;
        const float4 av = *reinterpret_cast<const float4*>(
            &x[(size_t)(m0 + arow) * IN + k0 + acol]);
        const float4 bv = *reinterpret_cast<const float4*>(
            &W1[(size_t)(n0 + arow) * IN + k0 + acol]);

        __syncthreads();  // previous compute done reading smem
        As[acol + 0][arow] = av.x;
        As[acol + 1][arow] = av.y;
        As[acol + 2][arow] = av.z;
        As[acol + 3][arow] = av.w;
        Bs[acol + 0][arow] = bv.x;
        Bs[acol + 1][arow] = bv.y;
        Bs[acol + 2][arow] = bv.z;
        Bs[acol + 3][arow] = bv.w;
        __syncthreads();

#pragma unroll
        for (int kk = 0; kk < BK1; kk++) {
            const float4 a0 = *reinterpret_cast<const float4*>(&As[kk][ty * 4]);
            const float4 a1 = *reinterpret_cast<const float4*>(&As[kk][ty * 4 + 64]);
            const float4 bb0 = *reinterpret_cast<const float4*>(&Bs[kk][tx * 4]);
            const float4 bb1 = *reinterpret_cast<const float4*>(&Bs[kk][tx * 4 + 64]);
            const float ra[8] = {a0.x, a0.y, a0.z, a0.w, a1.x, a1.y, a1.z, a1.w};
            const float rb[8] = {bb0.x, bb0.y, bb0.z, bb0.w, bb1.x, bb1.y, bb1.z, bb1.w};
#pragma unroll
            for (int i = 0; i < 8; i++)
#pragma unroll
                for (int j = 0; j < 8; j++)
                    acc[i][j] += ra[i] * rb[j];
        }
    }

    // -------------------- fused LIF epilogue --------------------
    const float km  = 1.0f / tau_mem[0];   // dt/tau_mem, dt = 1
    const float ks  = 1.0f / tau_syn[0];   // dt/tau_syn
    const float vth = v_thresh[0];
    const float vre = v_reset[0];
    const int   T   = tsteps[0];
    const float fT  = (float)T;

#pragma unroll
    for (int i = 0; i < 8; i++) {
        const int lr = (i < 4) ? (ty * 4 + i) : (64 + ty * 4 + (i - 4));
        const int gm = m0 + lr;

        float cur[8], vv[8], ii[8], cnt[8];
        int   gn[8];
#pragma unroll
        for (int j = 0; j < 8; j++) {
            const int lc = (j < 4) ? (tx * 4 + j) : (64 + tx * 4 + (j - 4));
            gn[j]  = n0 + lc;
            cur[j] = (acc[i][j] + b1[gn[j]]) / fT;
            vv[j]  = v0[(size_t)gm * H + gn[j]];
            ii[j]  = i0[(size_t)gm * H + gn[j]];
            cnt[j] = 0.0f;
        }
        // 8 independent chains per step -> hides the 4-cycle FFMA RAW latency
#pragma unroll 4
        for (int t = 0; t < T; t++) {
#pragma unroll
            for (int j = 0; j < 8; j++) {
                ii[j] = ii[j] - ks * ii[j] + cur[j];
                vv[j] = vv[j] - km * vv[j] + ii[j];
                if (vv[j] >= vth) { cnt[j] += 1.0f; vv[j] = vre; }
            }
        }
#pragma unroll
        for (int j = 0; j < 8; j++)
            spikes[(size_t)gm * H + gn[j]] = cnt[j];
    }
}

// ---------------------------------------------------------------------------
#define BM2 128
#define BN2 64
#define BK2 8

__global__ __launch_bounds__(256)
void snn_fc2_kernel(const float* __restrict__ spikes, // [B, H]
                    const float* __restrict__ W2,     // [OUT, H]
                    const float* __restrict__ b2,     // [OUT]
                    float* __restrict__ out,          // [B, OUT]
                    int Bn, int H, int OUT)
{
    __shared__ __align__(16) float As[BK2][BM2 + 4];
    __shared__ __align__(16) float Bs[BK2][BN2 + 4];

    const int tid = threadIdx.x;
    const int tx  = tid & 15;   // 16 x 4 cols = 64
    const int ty  = tid >> 4;   // 16 x 8 rows = 128
    const int m0  = blockIdx.y * BM2;
    const int n0  = blockIdx.x * BN2;

    const int arow = tid >> 1;        // 0..127
    const int acol = (tid & 1) * 4;   // 0/4
    const int brow = tid >> 2;        // 0..63
    const int bcol = (tid & 3) * 2;   // 0,2,4,6

    float acc[8][4];
#pragma unroll
    for (int i = 0; i < 8; i++)
#pragma unroll
        for (int j = 0; j < 4; j++) acc[i][j] = 0.0f;

    const int ktiles = H / BK2;
    for (int kt = 0; kt < ktiles; kt++) {
        const int k0 = kt * BK2;
        const float4 av = *reinterpret_cast<const float4*>(
            &spikes[(size_t)(m0 + arow) * H + k0 + acol]);
        const float2 bv = *reinterpret_cast<const float2*>(
            &W2[(size_t)(n0 + brow) * H + k0 + bcol]);

        __syncthreads();
        As[acol + 0][arow] = av.x;
        As[acol + 1][arow] = av.y;
        As[acol + 2][arow] = av.z;
        As[acol + 3][arow] = av.w;
        Bs[bcol + 0][brow] = bv.x;
        Bs[bcol + 1][brow] = bv.y;
        __syncthreads();

#pragma unroll
        for (int kk = 0; kk < BK2; kk++) {
            const float4 a0 = *reinterpret_cast<const float4*>(&As[kk][ty * 8]);
            const float4 a1 = *reinterpret_cast<const float4*>(&As[kk][ty * 8 + 4]);
            const float4 bb = *reinterpret_cast<const float4*>(&Bs[kk][tx * 4]);
            const float ra[8] = {a0.x, a0.y, a0.z, a0.w, a1.x, a1.y, a1.z, a1.w};
            const float rb[4] = {bb.x, bb.y, bb.z, bb.w};
#pragma unroll
            for (int i = 0; i < 8; i++)
#pragma unroll
                for (int j = 0; j < 4; j++)
                    acc[i][j] += ra[i] * rb[j];
        }
    }

#pragma unroll
    for (int i = 0; i < 8; i++) {
        const int gm = m0 + ty * 8 + i;
#pragma unroll
        for (int j = 0; j < 4; j++) {
            const int gn = n0 + tx * 4 + j;
            out[(size_t)gm * OUT + gn] = acc[i][j] + b2[gn];
        }
    }
}

// ---------------------------------------------------------------------------
extern "C" void kernel_launch(void* const* d_in, const int* in_sizes, int n_in,
                              void* d_out, int out_size)
{
    const float* x        = (const float*)d_in[0];
    const float* W1       = (const float*)d_in[1];
    const float* b1       = (const float*)d_in[2];
    const float* W2       = (const float*)d_in[3];
    const float* b2       = (const float*)d_in[4];
    const float* tau_mem  = (const float*)d_in[5];
    const float* tau_syn  = (const float*)d_in[6];
    const float* v_thresh = (const float*)d_in[7];
    const float* v_reset  = (const float*)d_in[8];
    const float* v0       = (const float*)d_in[9];
    const float* i0       = (const float*)d_in[10];
    const int*   tsteps   = (const int*)d_in[11];   // low 32 bits correct for i32/i64 LE

    const int H   = in_sizes[2];            // 2048
    const int IN  = in_sizes[1] / H;        // 1024
    const int Bn  = in_sizes[0] / IN;       // 4096
    const int OUT = in_sizes[4];            // 256

    float* out    = (float*)d_out;                  // [B, OUT] first
    float* spikes = out + (size_t)Bn * OUT;         // then [B, H]

    dim3 g1(H / BN1, Bn / BM1);
    snn_fc1_lif_kernel<<<g1, 256>>>(x, W1, b1, tau_mem, tau_syn, v_thresh,
                                    v_reset, v0, i0, tsteps, spikes, Bn, IN, H);

    dim3 g2(OUT / BN2, Bn / BM2);
    snn_fc2_kernel<<<g2, 256>>>(spikes, W2, b2, out, Bn, H, OUT);
}

// round 2
// speedup vs baseline: 1.0732x; 1.0732x over previous
#include <cuda_runtime.h>
#include <cuda_bf16.h>

// ---------------------------------------------------------------------------
// SimpleSNN: cur=(x@W1^T+b1)/T -> 32-step LIF -> total_spikes -> @W2^T+b2
// d_out layout: [ output (B*OUT) | total_spikes (B*H) ]
// R2: double-buffered smem pipelines for both GEMMs; fc2 retiled for occupancy.
// fc1 accumulation stays a single ascending-k FFMA chain (bit-identical to R1).
// ---------------------------------------------------------------------------

#define BM1 128
#define BN1 128
#define BK1 16

__global__ __launch_bounds__(256)
void snn_fc1_lif_kernel(const float* __restrict__ x,     // [B, IN]
                        const float* __restrict__ W1,    // [H, IN]
                        const float* __restrict__ b1,    // [H]
                        const float* __restrict__ tau_mem,
                        const float* __restrict__ tau_syn,
                        const float* __restrict__ v_thresh,
                        const float* __restrict__ v_reset,
                        const float* __restrict__ v0,    // [B, H]
                        const float* __restrict__ i0,    // [B, H]
                        const int*   __restrict__ tsteps,
                        float* __restrict__ spikes,      // [B, H]
                        int Bn, int IN, int H)
{
    __shared__ __align__(16) float As[2][BK1][BM1 + 4];
    __shared__ __align__(16) float Bs[2][BK1][BN1 + 4];

    const int tid = threadIdx.x;
    const int tx  = tid & 15;   // col group
    const int ty  = tid >> 4;   // row group
    const int m0  = blockIdx.y * BM1;
    const int n0  = blockIdx.x * BN1;

    // global-load mapping: 2 float4 per matrix per thread per BK1=16 tile
    const int arow = tid >> 2;        // 0..63 (and +64)
    const int acol = (tid & 3) * 4;   // 0,4,8,12

    const float* xA = &x [(size_t)(m0 + arow) * IN + acol];
    const float* xB = &x [(size_t)(m0 + arow + 64) * IN + acol];
    const float* wA = &W1[(size_t)(n0 + arow) * IN + acol];
    const float* wB = &W1[(size_t)(n0 + arow + 64) * IN + acol];

    float acc[8][8];
#pragma unroll
    for (int i = 0; i < 8; i++)
#pragma unroll
        for (int j = 0; j < 8; j++) acc[i][j] = 0.0f;

    // preload tile 0
    float4 a0v = *reinterpret_cast<const float4*>(xA);
    float4 a1v = *reinterpret_cast<const float4*>(xB);
    float4 b0v = *reinterpret_cast<const float4*>(wA);
    float4 b1v = *reinterpret_cast<const float4*>(wB);
#pragma unroll
    for (int c = 0; c < 4; c++) {
        As[0][acol + c][arow]      = (&a0v.x)[c];
        As[0][acol + c][arow + 64] = (&a1v.x)[c];
        Bs[0][acol + c][arow]      = (&b0v.x)[c];
        Bs[0][acol + c][arow + 64] = (&b1v.x)[c];
    }
    __syncthreads();

    const int ktiles = IN / BK1;
    for (int kt = 0; kt < ktiles; kt++) {
        const int buf = kt & 1;
        if (kt + 1 < ktiles) {
            const int k0 = (kt + 1) * BK1;
            a0v = *reinterpret_cast<const float4*>(xA + k0);
            a1v = *reinterpret_cast<const float4*>(xB + k0);
            b0v = *reinterpret_cast<const float4*>(wA + k0);
            b1v = *reinterpret_cast<const float4*>(wB + k0);
        }
#pragma unroll
        for (int kk = 0; kk < BK1; kk++) {
            const float4 ra0 = *reinterpret_cast<const float4*>(&As[buf][kk][ty * 4]);
            const float4 ra1 = *reinterpret_cast<const float4*>(&As[buf][kk][ty * 4 + 64]);
            const float4 rb0 = *reinterpret_cast<const float4*>(&Bs[buf][kk][tx * 4]);
            const float4 rb1 = *reinterpret_cast<const float4*>(&Bs[buf][kk][tx * 4 + 64]);
            const float ra[8] = {ra0.x, ra0.y, ra0.z, ra0.w, ra1.x, ra1.y, ra1.z, ra1.w};
            const float rb[8] = {rb0.x, rb0.y, rb0.z, rb0.w, rb1.x, rb1.y, rb1.z, rb1.w};
#pragma unroll
            for (int i = 0; i < 8; i++)
#pragma unroll
                for (int j = 0; j < 8; j++)
                    acc[i][j] += ra[i] * rb[j];
        }
        if (kt + 1 < ktiles) {
            const int nb = buf ^ 1;
#pragma unroll
            for (int c = 0; c < 4; c++) {
                As[nb][acol + c][arow]      = (&a0v.x)[c];
                As[nb][acol + c][arow + 64] = (&a1v.x)[c];
                Bs[nb][acol + c][arow]      = (&b0v.x)[c];
                Bs[nb][acol + c][arow + 64] = (&b1v.x)[c];
            }
            __syncthreads();
        }
    }

    // -------------------- fused LIF epilogue (unchanged numerics) ------------
    const float km  = 1.0f / tau_mem[0];
    const float ks  = 1.0f / tau_syn[0];
    const float vth = v_thresh[0];
    const float vre = v_reset[0];
    const int   T   = tsteps[0];
    const float fT  = (float)T;

#pragma unroll
    for (int i = 0; i < 8; i++) {
        const int lr = (i < 4) ? (ty * 4 + i) : (64 + ty * 4 + (i - 4));
        const int gm = m0 + lr;

        float cur[8], vv[8], ii[8], cnt[8];
        int   gn[8];
#pragma unroll
        for (int j = 0; j < 8; j++) {
            const int lc = (j < 4) ? (tx * 4 + j) : (64 + tx * 4 + (j - 4));
            gn[j]  = n0 + lc;
            cur[j] = (acc[i][j] + b1[gn[j]]) / fT;
            vv[j]  = v0[(size_t)gm * H + gn[j]];
            ii[j]  = i0[(size_t)gm * H + gn[j]];
            cnt[j] = 0.0f;
        }
#pragma unroll 4
        for (int t = 0; t < T; t++) {
#pragma unroll
            for (int j = 0; j < 8; j++) {
                ii[j] = ii[j] - ks * ii[j] + cur[j];
                vv[j] = vv[j] - km * vv[j] + ii[j];
                if (vv[j] >= vth) { cnt[j] += 1.0f; vv[j] = vre; }
            }
        }
#pragma unroll
        for (int j = 0; j < 8; j++)
            spikes[(size_t)gm * H + gn[j]] = cnt[j];
    }
}

// ---------------------------------------------------------------------------
// fc2: 64x64 tiles, BK=16, 256 threads, 4x4 microtile, double-buffered.
// grid = (OUT/64=4) x (B/64=64) = 256 blocks -> multiple blocks/SM.
// ---------------------------------------------------------------------------
#define BM2 64
#define BN2 64
#define BK2 16

__global__ __launch_bounds__(256)
void snn_fc2_kernel(const float* __restrict__ spikes, // [B, H]
                    const float* __restrict__ W2,     // [OUT, H]
                    const float* __restrict__ b2,     // [OUT]
                    float* __restrict__ out,          // [B, OUT]
                    int Bn, int H, int OUT)
{
    __shared__ __align__(16) float As[2][BK2][BM2 + 4];
    __shared__ __align__(16) float Bs[2][BK2][BN2 + 4];

    const int tid = threadIdx.x;
    const int tx  = tid & 15;   // 16 cols of 4
    const int ty  = tid >> 4;   // 16 rows of 4
    const int m0  = blockIdx.y * BM2;
    const int n0  = blockIdx.x * BN2;

    const int arow = tid >> 2;        // 0..63
    const int acol = (tid & 3) * 4;   // 0,4,8,12

    const float* sA = &spikes[(size_t)(m0 + arow) * H + acol];
    const float* wA = &W2    [(size_t)(n0 + arow) * H + acol];

    float acc[4][4];
#pragma unroll
    for (int i = 0; i < 4; i++)
#pragma unroll
        for (int j = 0; j < 4; j++) acc[i][j] = 0.0f;

    float4 av = *reinterpret_cast<const float4*>(sA);
    float4 bv = *reinterpret_cast<const float4*>(wA);
#pragma unroll
    for (int c = 0; c < 4; c++) {
        As[0][acol + c][arow] = (&av.x)[c];
        Bs[0][acol + c][arow] = (&bv.x)[c];
    }
    __syncthreads();

    const int ktiles = H / BK2;
    for (int kt = 0; kt < ktiles; kt++) {
        const int buf = kt & 1;
        if (kt + 1 < ktiles) {
            const int k0 = (kt + 1) * BK2;
            av = *reinterpret_cast<const float4*>(sA + k0);
            bv = *reinterpret_cast<const float4*>(wA + k0);
        }
#pragma unroll
        for (int kk = 0; kk < BK2; kk++) {
            const float4 ra4 = *reinterpret_cast<const float4*>(&As[buf][kk][ty * 4]);
            const float4 rb4 = *reinterpret_cast<const float4*>(&Bs[buf][kk][tx * 4]);
            const float ra[4] = {ra4.x, ra4.y, ra4.z, ra4.w};
            const float rb[4] = {rb4.x, rb4.y, rb4.z, rb4.w};
#pragma unroll
            for (int i = 0; i < 4; i++)
#pragma unroll
                for (int j = 0; j < 4; j++)
                    acc[i][j] += ra[i] * rb[j];
        }
        if (kt + 1 < ktiles) {
            const int nb = buf ^ 1;
#pragma unroll
            for (int c = 0; c < 4; c++) {
                As[nb][acol + c][arow] = (&av.x)[c];
                Bs[nb][acol + c][arow] = (&bv.x)[c];
            }
            __syncthreads();
        }
    }

#pragma unroll
    for (int i = 0; i < 4; i++) {
        const int gm = m0 + ty * 4 + i;
#pragma unroll
        for (int j = 0; j < 4; j++) {
            const int gn = n0 + tx * 4 + j;
            out[(size_t)gm * OUT + gn] = acc[i][j] + b2[gn];
        }
    }
}

// ---------------------------------------------------------------------------
extern "C" void kernel_launch(void* const* d_in, const int* in_sizes, int n_in,
                              void* d_out, int out_size)
{
    const float* x        = (const float*)d_in[0];
    const float* W1       = (const float*)d_in[1];
    const float* b1       = (const float*)d_in[2];
    const float* W2       = (const float*)d_in[3];
    const float* b2       = (const float*)d_in[4];
    const float* tau_mem  = (const float*)d_in[5];
    const float* tau_syn  = (const float*)d_in[6];
    const float* v_thresh = (const float*)d_in[7];
    const float* v_reset  = (const float*)d_in[8];
    const float* v0       = (const float*)d_in[9];
    const float* i0       = (const float*)d_in[10];
    const int*   tsteps   = (const int*)d_in[11];

    const int H   = in_sizes[2];            // 2048
    const int IN  = in_sizes[1] / H;        // 1024
    const int Bn  = in_sizes[0] / IN;       // 4096
    const int OUT = in_sizes[4];            // 256

    float* out    = (float*)d_out;
    float* spikes = out + (size_t)Bn * OUT;

    dim3 g1(H / BN1, Bn / BM1);
    snn_fc1_lif_kernel<<<g1, 256>>>(x, W1, b1, tau_mem, tau_syn, v_thresh,
                                    v_reset, v0, i0, tsteps, spikes, Bn, IN, H);

    dim3 g2(OUT / BN2, Bn / BM2);
    snn_fc2_kernel<<<g2, 256>>>(spikes, W2, b2, out, Bn, H, OUT);
}